// round 3
// baseline (speedup 1.0000x reference)
// CrossLayerTranscoder — tf32 mma.sync GEMM, producer-side tf32 conversion,
// paired-k SMEM layout (LDS.64 fragments), 2-stage smem + register pipeline.
//
// encode: feats[l] = relu(resid[l] @ enc_w[l]^T)            M=2048,N=512,K=2048
// decode: recon[t] = sum_{s<=t} feats[s] @ dec_w[s,t]^T     M=2048,N=2048,K=(t+1)*512

#include <cuda_runtime.h>
#include <cstdint>
#include <cstddef>

#define L_DIM 16
#define BS_DIM 2048
#define H_DIM 2048
#define F_DIM 512

#define TM 128
#define TN 128
#define TK 32
#define NTHREADS 256

#define A_BYTES (TM * TK * 4)            // 16 KB
#define STAGE_BYTES (2 * A_BYTES)        // 32 KB (A + B)
#define SMEM_BYTES (2 * STAGE_BYTES)     // 64 KB, double buffered

__device__ __forceinline__ uint32_t smem_u32(const void* p) {
    uint32_t a;
    asm("{ .reg .u64 t; cvta.to.shared.u64 t, %1; cvt.u32.u64 %0, t; }" : "=r"(a) : "l"(p));
    return a;
}
__device__ __forceinline__ uint32_t f2tf32(float x) {
    uint32_t r; asm("cvt.rna.tf32.f32 %0, %1;" : "=r"(r) : "f"(x)); return r;
}
__device__ __forceinline__ void sts128(uint32_t addr, uint32_t v0, uint32_t v1,
                                       uint32_t v2, uint32_t v3) {
    asm volatile("st.shared.v4.b32 [%0], {%1,%2,%3,%4};"
                 :: "r"(addr), "r"(v0), "r"(v1), "r"(v2), "r"(v3) : "memory");
}
__device__ __forceinline__ void lds64(uint32_t addr, uint32_t& d0, uint32_t& d1) {
    asm volatile("ld.shared.v2.u32 {%0,%1}, [%2];" : "=r"(d0), "=r"(d1) : "r"(addr));
}
__device__ __forceinline__ void mma_tf32(float* c, const uint32_t* a, const uint32_t* b) {
    asm volatile(
        "mma.sync.aligned.m16n8k8.row.col.f32.tf32.tf32.f32 "
        "{%0,%1,%2,%3}, {%4,%5,%6,%7}, {%8,%9}, {%0,%1,%2,%3};"
        : "+f"(c[0]), "+f"(c[1]), "+f"(c[2]), "+f"(c[3])
        : "r"(a[0]), "r"(a[1]), "r"(a[2]), "r"(a[3]), "r"(b[0]), "r"(b[1]));
}

// SMEM tile layout (per 128x32 tile, u32 elements):
//   pos(k) = (k>>3)*8 + (k&3)*2 + ((k>>2)&1)   -> (k, k+4) adjacent pairs
//   addr   = row*128B + ((pos>>2) ^ (row&7))*16B + (pos&3)*4B
// Fragment (row, ks, t): pos = ks*8 + 2t -> chunk = (2ks + (t>>1)) ^ (row&7),
// byte-in-chunk = 8*(t&1); one LDS.64 returns (k=ks*8+t, k+4).

template <bool ENCODE>
__global__ __launch_bounds__(NTHREADS, 1)
void clt_gemm(const float* __restrict__ gA, const float* __restrict__ gB,
              float* __restrict__ gOut) {
    extern __shared__ char smem[];
    const uint32_t sbase = smem_u32(smem);
    const int tid  = threadIdx.x;
    const int lane = tid & 31;
    const int w    = tid >> 5;
    const int wm   = w & 3;            // 4 warps along M (32 rows each)
    const int wn   = w >> 2;           // 2 warps along N (64 cols each)
    const int r8   = lane >> 2;
    const int t    = lane & 3;
    const int t_hi = t >> 1;
    const int t_lo = t & 1;
    const int m0   = blockIdx.x * TM;
    const int n0   = blockIdx.y * TN;
    const int z    = blockIdx.z;
    const int iters = ENCODE ? (H_DIM / TK) : ((z + 1) * (F_DIM / TK));

    float acc[2][8][4];
    #pragma unroll
    for (int mt = 0; mt < 2; mt++)
        #pragma unroll
        for (int nt = 0; nt < 8; nt++)
            #pragma unroll
            for (int r = 0; r < 4; r++) acc[mt][nt][r] = 0.0f;

    // ---------- producer state: one global row per thread ----------
    const int  lrow = tid & 127;
    const bool isB  = tid >= 128;
    float4 f4[8];
    const float* rowbase;
    if (ENCODE) {
        rowbase = isB ? gB + ((size_t)z * F_DIM + n0 + lrow) * H_DIM
                      : gA + ((size_t)z * BS_DIM + m0 + lrow) * H_DIM;
    } else {
        rowbase = isB ? gB + ((size_t)z * H_DIM + n0 + lrow) * F_DIM          // dec_w[0][z] row
                      : gA + ((size_t)(m0 + lrow)) * F_DIM;                   // feats[0] row
    }

    auto ldg_regs = [&](int fi) {
        const float* src;
        if (ENCODE) {
            src = rowbase + fi * TK;
        } else {
            int s  = fi >> 4;                 // source layer
            int kb = (fi & 15) * TK;
            size_t soff = isB ? (size_t)s * L_DIM * H_DIM * F_DIM
                              : (size_t)s * BS_DIM * F_DIM;
            src = rowbase + soff + kb;
        }
        #pragma unroll
        for (int j = 0; j < 8; j++) f4[j] = *(const float4*)(src + j * 4);
    };

    const uint32_t sts_base0 = sbase + (isB ? A_BYTES : 0) + lrow * 128;
    const int xr = lrow & 7;
    auto sts_stage = [&](int slot) {
        const float* f = (const float*)f4;
        uint32_t base = sts_base0 + (uint32_t)slot * STAGE_BYTES;
        #pragma unroll
        for (int c = 0; c < 8; c++) {
            const int kb = (c >> 1) * 8 + (c & 1) * 2;
            sts128(base + ((c ^ xr) << 4),
                   f2tf32(f[kb]), f2tf32(f[kb + 4]),
                   f2tf32(f[kb + 1]), f2tf32(f[kb + 5]));
        }
    };

    // ---------- consumer fragment loads ----------
    // per-thread fixed pieces of the fragment address
    const uint32_t a_row0 = (uint32_t)(wm * 32 + r8) * 128 + 8u * t_lo;
    const uint32_t b_row0 = (uint32_t)(wn * 64 + r8) * 128 + 8u * t_lo;

    uint32_t af[2][2][4], bf[2][8][2];
    auto load_frags = [&](uint32_t slotbase, int ks, int cb) {
        const uint32_t aB = slotbase;
        const uint32_t bB = slotbase + A_BYTES;
        const uint32_t cx = (uint32_t)(((2 * ks + t_hi) ^ r8) << 4);
        #pragma unroll
        for (int mt = 0; mt < 2; mt++) {
            uint32_t base = aB + a_row0 + (uint32_t)(mt * 16) * 128 + cx;
            lds64(base,            af[cb][mt][0], af[cb][mt][2]);   // row r   : (k, k+4)
            lds64(base + 8 * 128,  af[cb][mt][1], af[cb][mt][3]);   // row r+8
        }
        #pragma unroll
        for (int nt = 0; nt < 8; nt++) {
            lds64(bB + b_row0 + (uint32_t)(nt * 8) * 128 + cx,
                  bf[cb][nt][0], bf[cb][nt][1]);
        }
    };

    // ---------- pipeline prologue ----------
    ldg_regs(0);
    sts_stage(0);
    if (iters > 1) ldg_regs(1);
    __syncthreads();

    // ---------- mainloop ----------
    for (int i = 0; i < iters; i++) {
        if (i + 1 < iters) sts_stage((i + 1) & 1);
        if (i + 2 < iters) ldg_regs(i + 2);

        const uint32_t slotbase = sbase + (uint32_t)(i & 1) * STAGE_BYTES;
        load_frags(slotbase, 0, 0);
        #pragma unroll
        for (int ks = 0; ks < 4; ks++) {
            const int cb = ks & 1;
            if (ks < 3) load_frags(slotbase, ks + 1, cb ^ 1);
            #pragma unroll
            for (int mt = 0; mt < 2; mt++)
                #pragma unroll
                for (int nt = 0; nt < 8; nt++)
                    mma_tf32(acc[mt][nt], af[cb][mt], bf[cb][nt]);
        }
        __syncthreads();
    }

    // ---------- epilogue: direct float2 stores ----------
    const int ldo = ENCODE ? F_DIM : H_DIM;
    float* ob = gOut + (size_t)z * BS_DIM * ldo;
    #pragma unroll
    for (int mt = 0; mt < 2; mt++) {
        #pragma unroll
        for (int nt = 0; nt < 8; nt++) {
            int row = m0 + wm * 32 + mt * 16 + r8;
            int col = n0 + wn * 64 + nt * 8 + t * 2;
            float v0 = acc[mt][nt][0], v1 = acc[mt][nt][1];
            float v2 = acc[mt][nt][2], v3 = acc[mt][nt][3];
            if (ENCODE) {
                v0 = fmaxf(v0, 0.0f); v1 = fmaxf(v1, 0.0f);
                v2 = fmaxf(v2, 0.0f); v3 = fmaxf(v3, 0.0f);
            }
            *(float2*)&ob[(size_t)row * ldo + col]       = make_float2(v0, v1);
            *(float2*)&ob[(size_t)(row + 8) * ldo + col] = make_float2(v2, v3);
        }
    }
}

extern "C" void kernel_launch(void* const* d_in, const int* in_sizes, int n_in,
                              void* d_out, int out_size) {
    (void)in_sizes; (void)n_in; (void)out_size;
    const float* resid = (const float*)d_in[0];   // [L, B, S, H]
    const float* enc_w = (const float*)d_in[1];   // [L, F, H]
    const float* dec_w = (const float*)d_in[2];   // [L, L, H, F]
    float* out   = (float*)d_out;
    float* feats = out;                                   // [L, BS, F]
    float* recon = out + (size_t)L_DIM * BS_DIM * F_DIM;  // [L, BS, H]

    cudaFuncSetAttribute(clt_gemm<true>,  cudaFuncAttributeMaxDynamicSharedMemorySize, SMEM_BYTES);
    cudaFuncSetAttribute(clt_gemm<false>, cudaFuncAttributeMaxDynamicSharedMemorySize, SMEM_BYTES);

    dim3 grid_enc(BS_DIM / TM, F_DIM / TN, L_DIM);   // 16 x 4 x 16
    clt_gemm<true><<<grid_enc, NTHREADS, SMEM_BYTES>>>(resid, enc_w, feats);

    dim3 grid_dec(BS_DIM / TM, H_DIM / TN, L_DIM);   // 16 x 16 x 16
    clt_gemm<false><<<grid_dec, NTHREADS, SMEM_BYTES>>>(feats, dec_w, recon);
}

// round 4
// speedup vs baseline: 2.3205x; 2.3205x over previous
// CrossLayerTranscoder — tf32 mma.sync GEMM, cp.async (L1-bypass) pipeline,
// 64x64 warp tiles to cut issue-slots per MMA (R2 was issue-bound at 4.4 instr/MMA).
//
// encode: feats[l] = relu(resid[l] @ enc_w[l]^T)            M=2048,N=512,K=2048
// decode: recon[t] = sum_{s<=t} feats[s] @ dec_w[s,t]^T     M=2048,N=2048,K=(t+1)*512
//
// CTA 128x256x32, 3-stage cp.async pipeline, 8 warps (2Mx4N) of 64x64,
// m16n8k8 tf32 mma with consumer-side cvt.rna, XOR-swizzled SMEM (conflict-free).

#include <cuda_runtime.h>
#include <cstdint>
#include <cstddef>

#define L_DIM 16
#define BS_DIM 2048
#define H_DIM 2048
#define F_DIM 512

#define TM 128
#define TN 256
#define TK 32
#define STAGES 3
#define NTHREADS 256

#define A_FLOATS (TM * TK)                   // 4096 (16 KB)
#define B_FLOATS (TN * TK)                   // 8192 (32 KB)
#define STAGE_FLOATS (A_FLOATS + B_FLOATS)   // 12288 (48 KB)
#define SMEM_BYTES (STAGES * STAGE_FLOATS * 4)   // 147456
#define A_CHUNKS (TM * 8)                    // 1024 x 16B
#define STAGE_CHUNKS (STAGE_FLOATS / 4)      // 3072

__device__ __forceinline__ uint32_t smem_u32(const void* p) {
    uint32_t a;
    asm("{ .reg .u64 t; cvta.to.shared.u64 t, %1; cvt.u32.u64 %0, t; }" : "=r"(a) : "l"(p));
    return a;
}
__device__ __forceinline__ void cp_async16(uint32_t dst, const float* src) {
    asm volatile("cp.async.cg.shared.global [%0], [%1], 16;" :: "r"(dst), "l"(src));
}
__device__ __forceinline__ void cp_commit() { asm volatile("cp.async.commit_group;"); }
template <int N> __device__ __forceinline__ void cp_wait() {
    asm volatile("cp.async.wait_group %0;" :: "n"(N));
}
__device__ __forceinline__ uint32_t f2tf32(float x) {
    uint32_t r; asm("cvt.rna.tf32.f32 %0, %1;" : "=r"(r) : "f"(x)); return r;
}
__device__ __forceinline__ void mma_tf32(float* c, const uint32_t* a, const uint32_t* b) {
    asm volatile(
        "mma.sync.aligned.m16n8k8.row.col.f32.tf32.tf32.f32 "
        "{%0,%1,%2,%3}, {%4,%5,%6,%7}, {%8,%9}, {%0,%1,%2,%3};"
        : "+f"(c[0]), "+f"(c[1]), "+f"(c[2]), "+f"(c[3])
        : "r"(a[0]), "r"(a[1]), "r"(a[2]), "r"(a[3]), "r"(b[0]), "r"(b[1]));
}

// swizzled float index within one tile (row-major 32 floats/row, 8x16B chunks):
// chunk c = (k>>2) ^ (row&7), word = k&3. Conflict-free for cp.async row writes
// and for m16n8k8 fragment LDS.32 reads (verified bank arithmetic).
__device__ __forceinline__ int sidx(int row, int k) {
    return (((row << 3) + ((k >> 2) ^ (row & 7))) << 2) + (k & 3);
}

template <bool ENCODE>
__global__ __launch_bounds__(NTHREADS, 1)
void clt_gemm(const float* __restrict__ gA, const float* __restrict__ gB,
              float* __restrict__ gOut) {
    extern __shared__ float smem[];
    const int tid  = threadIdx.x;
    const int lane = tid & 31;
    const int w    = tid >> 5;
    const int wm   = w & 1;        // 2 warps along M (64 rows each)
    const int wn   = w >> 1;       // 4 warps along N (64 cols each)
    const int r8   = lane >> 2;
    const int t    = lane & 3;
    const int m0   = blockIdx.x * TM;
    const int n0   = blockIdx.y * TN;
    const int z    = blockIdx.z;
    const int iters = ENCODE ? (H_DIM / TK) : ((z + 1) * (F_DIM / TK));

    const uint32_t sbase = smem_u32(smem);

    float acc[4][8][4];
    #pragma unroll
    for (int mt = 0; mt < 4; mt++)
        #pragma unroll
        for (int nt = 0; nt < 8; nt++)
            #pragma unroll
            for (int r = 0; r < 4; r++) acc[mt][nt][r] = 0.0f;

    // ---- stage loader: 3072 x 16B chunks, 12 per thread, cp.async (L1 bypass) ----
    auto load_stage = [&](int fi, int slot) {
        int kbase, lda, ldb;
        const float *Ab, *Bb;
        if (ENCODE) {
            kbase = fi * TK;
            Ab = gA + (size_t)z * BS_DIM * H_DIM;
            Bb = gB + (size_t)z * F_DIM * H_DIM;
            lda = H_DIM; ldb = H_DIM;
        } else {
            int s  = fi >> 4;
            kbase  = (fi & 15) * TK;
            Ab = gA + (size_t)s * BS_DIM * F_DIM;
            Bb = gB + ((size_t)s * L_DIM + z) * (size_t)H_DIM * F_DIM;
            lda = F_DIM; ldb = F_DIM;
        }
        uint32_t sA = sbase + (uint32_t)slot * STAGE_FLOATS * 4;
        uint32_t sB = sA + A_FLOATS * 4;
        #pragma unroll
        for (int j = 0; j < STAGE_CHUNKS / NTHREADS; j++) {
            int q   = j * NTHREADS + tid;
            int isB = q >= A_CHUNKS;
            int qq  = isB ? q - A_CHUNKS : q;
            int row = qq >> 3;
            int c   = qq & 7;
            const float* src = (isB ? Bb + (size_t)(n0 + row) * ldb
                                    : Ab + (size_t)(m0 + row) * lda) + kbase + c * 4;
            uint32_t dst = (isB ? sB : sA) + ((((row << 3) + (c ^ (row & 7)))) << 4);
            cp_async16(dst, src);
        }
        cp_commit();
    };

    // ---- prologue ----
    int fetch = 0;
    #pragma unroll
    for (int s = 0; s < STAGES - 1; s++) { load_stage(fetch, fetch % STAGES); fetch++; }

    // ---- mainloop ----
    for (int i = 0; i < iters; i++) {
        cp_wait<STAGES - 2>();
        __syncthreads();
        if (fetch < iters) { load_stage(fetch, fetch % STAGES); fetch++; }

        const float* sA = smem + (size_t)(i % STAGES) * STAGE_FLOATS;
        const float* sB = sA + A_FLOATS;

        #pragma unroll
        for (int ks = 0; ks < 4; ks++) {
            const int kk = ks * 8 + t;
            uint32_t af[4][4], bf[8][2];
            #pragma unroll
            for (int mt = 0; mt < 4; mt++) {
                int r = wm * 64 + mt * 16 + r8;
                af[mt][0] = f2tf32(sA[sidx(r,     kk)]);
                af[mt][1] = f2tf32(sA[sidx(r + 8, kk)]);
                af[mt][2] = f2tf32(sA[sidx(r,     kk + 4)]);
                af[mt][3] = f2tf32(sA[sidx(r + 8, kk + 4)]);
            }
            #pragma unroll
            for (int nt = 0; nt < 8; nt++) {
                int n = wn * 64 + nt * 8 + r8;
                bf[nt][0] = f2tf32(sB[sidx(n, kk)]);
                bf[nt][1] = f2tf32(sB[sidx(n, kk + 4)]);
            }
            #pragma unroll
            for (int mt = 0; mt < 4; mt++)
                #pragma unroll
                for (int nt = 0; nt < 8; nt++)
                    mma_tf32(acc[mt][nt], af[mt], bf[nt]);
        }
        __syncthreads();
    }

    // ---- epilogue: direct float2 stores ----
    const int ldo = ENCODE ? F_DIM : H_DIM;
    float* ob = gOut + (size_t)z * BS_DIM * ldo;
    #pragma unroll
    for (int mt = 0; mt < 4; mt++) {
        #pragma unroll
        for (int nt = 0; nt < 8; nt++) {
            int row = m0 + wm * 64 + mt * 16 + r8;
            int col = n0 + wn * 64 + nt * 8 + t * 2;
            float v0 = acc[mt][nt][0], v1 = acc[mt][nt][1];
            float v2 = acc[mt][nt][2], v3 = acc[mt][nt][3];
            if (ENCODE) {
                v0 = fmaxf(v0, 0.0f); v1 = fmaxf(v1, 0.0f);
                v2 = fmaxf(v2, 0.0f); v3 = fmaxf(v3, 0.0f);
            }
            *(float2*)&ob[(size_t)row * ldo + col]       = make_float2(v0, v1);
            *(float2*)&ob[(size_t)(row + 8) * ldo + col] = make_float2(v2, v3);
        }
    }
}

extern "C" void kernel_launch(void* const* d_in, const int* in_sizes, int n_in,
                              void* d_out, int out_size) {
    (void)in_sizes; (void)n_in; (void)out_size;
    const float* resid = (const float*)d_in[0];   // [L, B, S, H]
    const float* enc_w = (const float*)d_in[1];   // [L, F, H]
    const float* dec_w = (const float*)d_in[2];   // [L, L, H, F]
    float* out   = (float*)d_out;
    float* feats = out;                                   // [L, BS, F]
    float* recon = out + (size_t)L_DIM * BS_DIM * F_DIM;  // [L, BS, H]

    cudaFuncSetAttribute(clt_gemm<true>,  cudaFuncAttributeMaxDynamicSharedMemorySize, SMEM_BYTES);
    cudaFuncSetAttribute(clt_gemm<false>, cudaFuncAttributeMaxDynamicSharedMemorySize, SMEM_BYTES);

    dim3 grid_enc(BS_DIM / TM, F_DIM / TN, L_DIM);   // 16 x 2 x 16
    clt_gemm<true><<<grid_enc, NTHREADS, SMEM_BYTES>>>(resid, enc_w, feats);

    dim3 grid_dec(BS_DIM / TM, H_DIM / TN, L_DIM);   // 16 x 8 x 16
    clt_gemm<false><<<grid_dec, NTHREADS, SMEM_BYTES>>>(feats, dec_w, recon);
}

// round 5
// speedup vs baseline: 2.5519x; 1.0997x over previous
// CrossLayerTranscoder — tf32 mma.sync GEMM, cp.async pipeline, 128-thread CTAs
// (2 CTAs/SM for decoupled barrier domains), 64x64 warp tiles, one barrier/iter,
// reversed-z scheduling to eliminate the decode straggler tail.
//
// encode: feats[l] = relu(resid[l] @ enc_w[l]^T)            M=2048,N=512,K=2048
// decode: recon[t] = sum_{s<=t} feats[s] @ dec_w[s,t]^T     M=2048,N=2048,K=(t+1)*512

#include <cuda_runtime.h>
#include <cstdint>
#include <cstddef>

#define L_DIM 16
#define BS_DIM 2048
#define H_DIM 2048
#define F_DIM 512

#define TM 128
#define TN 128
#define TK 32
#define STAGES 3
#define NTHREADS 128

#define A_FLOATS (TM * TK)                   // 4096 (16 KB)
#define B_FLOATS (TN * TK)                   // 4096 (16 KB)
#define STAGE_FLOATS (A_FLOATS + B_FLOATS)   // 8192 (32 KB)
#define SMEM_BYTES (STAGES * STAGE_FLOATS * 4)   // 98304 (96 KB)
#define A_CHUNKS (TM * 8)                    // 1024 x 16B
#define STAGE_CHUNKS (STAGE_FLOATS / 4)      // 2048

__device__ __forceinline__ uint32_t smem_u32(const void* p) {
    uint32_t a;
    asm("{ .reg .u64 t; cvta.to.shared.u64 t, %1; cvt.u32.u64 %0, t; }" : "=r"(a) : "l"(p));
    return a;
}
__device__ __forceinline__ void cp_async16(uint32_t dst, const float* src) {
    asm volatile("cp.async.cg.shared.global [%0], [%1], 16;" :: "r"(dst), "l"(src));
}
__device__ __forceinline__ void cp_commit() { asm volatile("cp.async.commit_group;"); }
template <int N> __device__ __forceinline__ void cp_wait() {
    asm volatile("cp.async.wait_group %0;" :: "n"(N));
}
__device__ __forceinline__ uint32_t f2tf32(float x) {
    uint32_t r; asm("cvt.rna.tf32.f32 %0, %1;" : "=r"(r) : "f"(x)); return r;
}
__device__ __forceinline__ void mma_tf32(float* c, const uint32_t* a, const uint32_t* b) {
    asm volatile(
        "mma.sync.aligned.m16n8k8.row.col.f32.tf32.tf32.f32 "
        "{%0,%1,%2,%3}, {%4,%5,%6,%7}, {%8,%9}, {%0,%1,%2,%3};"
        : "+f"(c[0]), "+f"(c[1]), "+f"(c[2]), "+f"(c[3])
        : "r"(a[0]), "r"(a[1]), "r"(a[2]), "r"(a[3]), "r"(b[0]), "r"(b[1]));
}

// swizzled float index within one tile (row-major 32 floats/row, 8x16B chunks):
// chunk = (k>>2) ^ (row&7), word = k&3. Conflict-free for cp.async row writes
// and for the m16n8k8 fragment LDS.32 reads.
__device__ __forceinline__ int sidx(int row, int k) {
    return (((row << 3) + ((k >> 2) ^ (row & 7))) << 2) + (k & 3);
}

template <bool ENCODE>
__global__ __launch_bounds__(NTHREADS, 2)
void clt_gemm(const float* __restrict__ gA, const float* __restrict__ gB,
              float* __restrict__ gOut) {
    extern __shared__ float smem[];
    const int tid  = threadIdx.x;
    const int lane = tid & 31;
    const int w    = tid >> 5;
    const int wm   = w & 1;        // 2 warps along M (64 rows each)
    const int wn   = w >> 1;       // 2 warps along N (64 cols each)
    const int r8   = lane >> 2;
    const int t    = lane & 3;
    const int m0   = blockIdx.x * TM;
    const int n0   = blockIdx.y * TN;
    const int z    = (int)gridDim.z - 1 - (int)blockIdx.z;   // heavy z first
    const int iters = ENCODE ? (H_DIM / TK) : ((z + 1) * (F_DIM / TK));

    const uint32_t sbase = smem_u32(smem);

    float acc[4][8][4];
    #pragma unroll
    for (int mt = 0; mt < 4; mt++)
        #pragma unroll
        for (int nt = 0; nt < 8; nt++)
            #pragma unroll
            for (int r = 0; r < 4; r++) acc[mt][nt][r] = 0.0f;

    // ---- stage loader: 2048 x 16B chunks, 16 per thread, cp.async (L1 bypass) ----
    auto load_stage = [&](int fi, int slot) {
        int kbase, lda, ldb;
        const float *Ab, *Bb;
        if (ENCODE) {
            kbase = fi * TK;
            Ab = gA + (size_t)z * BS_DIM * H_DIM;
            Bb = gB + (size_t)z * F_DIM * H_DIM;
            lda = H_DIM; ldb = H_DIM;
        } else {
            int s  = fi >> 4;
            kbase  = (fi & 15) * TK;
            Ab = gA + (size_t)s * BS_DIM * F_DIM;
            Bb = gB + ((size_t)s * L_DIM + z) * (size_t)H_DIM * F_DIM;
            lda = F_DIM; ldb = F_DIM;
        }
        uint32_t sA = sbase + (uint32_t)slot * STAGE_FLOATS * 4;
        uint32_t sB = sA + A_FLOATS * 4;
        #pragma unroll
        for (int j = 0; j < STAGE_CHUNKS / NTHREADS; j++) {
            int q   = j * NTHREADS + tid;
            int isB = q >= A_CHUNKS;
            int qq  = isB ? q - A_CHUNKS : q;
            int row = qq >> 3;
            int c   = qq & 7;
            const float* src = (isB ? Bb + (size_t)(n0 + row) * ldb
                                    : Ab + (size_t)(m0 + row) * lda) + kbase + c * 4;
            uint32_t dst = (isB ? sB : sA) + ((((row << 3) + (c ^ (row & 7)))) << 4);
            cp_async16(dst, src);
        }
        cp_commit();
    };

    // ---- prologue ----
    int fetch = 0;
    #pragma unroll
    for (int s = 0; s < STAGES - 1; s++) { load_stage(fetch, fetch % STAGES); fetch++; }

    // ---- mainloop: single barrier per iteration ----
    for (int i = 0; i < iters; i++) {
        cp_wait<STAGES - 2>();
        __syncthreads();   // stage i visible to all; all warps done reading slot (i+2)%3
        if (fetch < iters) { load_stage(fetch, fetch % STAGES); fetch++; }

        const float* sA = smem + (size_t)(i % STAGES) * STAGE_FLOATS;
        const float* sB = sA + A_FLOATS;

        #pragma unroll
        for (int ks = 0; ks < 4; ks++) {
            const int kk = ks * 8 + t;
            uint32_t af[4][4], bf[8][2];
            #pragma unroll
            for (int mt = 0; mt < 4; mt++) {
                int r = wm * 64 + mt * 16 + r8;
                af[mt][0] = f2tf32(sA[sidx(r,     kk)]);
                af[mt][1] = f2tf32(sA[sidx(r + 8, kk)]);
                af[mt][2] = f2tf32(sA[sidx(r,     kk + 4)]);
                af[mt][3] = f2tf32(sA[sidx(r + 8, kk + 4)]);
            }
            #pragma unroll
            for (int nt = 0; nt < 8; nt++) {
                int n = wn * 64 + nt * 8 + r8;
                bf[nt][0] = f2tf32(sB[sidx(n, kk)]);
                bf[nt][1] = f2tf32(sB[sidx(n, kk + 4)]);
            }
            #pragma unroll
            for (int mt = 0; mt < 4; mt++)
                #pragma unroll
                for (int nt = 0; nt < 8; nt++)
                    mma_tf32(acc[mt][nt], af[mt], bf[nt]);
        }
    }

    // ---- epilogue: direct float2 stores ----
    const int ldo = ENCODE ? F_DIM : H_DIM;
    float* ob = gOut + (size_t)z * BS_DIM * ldo;
    #pragma unroll
    for (int mt = 0; mt < 4; mt++) {
        #pragma unroll
        for (int nt = 0; nt < 8; nt++) {
            int row = m0 + wm * 64 + mt * 16 + r8;
            int col = n0 + wn * 64 + nt * 8 + t * 2;
            float v0 = acc[mt][nt][0], v1 = acc[mt][nt][1];
            float v2 = acc[mt][nt][2], v3 = acc[mt][nt][3];
            if (ENCODE) {
                v0 = fmaxf(v0, 0.0f); v1 = fmaxf(v1, 0.0f);
                v2 = fmaxf(v2, 0.0f); v3 = fmaxf(v3, 0.0f);
            }
            *(float2*)&ob[(size_t)row * ldo + col]       = make_float2(v0, v1);
            *(float2*)&ob[(size_t)(row + 8) * ldo + col] = make_float2(v2, v3);
        }
    }
}

extern "C" void kernel_launch(void* const* d_in, const int* in_sizes, int n_in,
                              void* d_out, int out_size) {
    (void)in_sizes; (void)n_in; (void)out_size;
    const float* resid = (const float*)d_in[0];   // [L, B, S, H]
    const float* enc_w = (const float*)d_in[1];   // [L, F, H]
    const float* dec_w = (const float*)d_in[2];   // [L, L, H, F]
    float* out   = (float*)d_out;
    float* feats = out;                                   // [L, BS, F]
    float* recon = out + (size_t)L_DIM * BS_DIM * F_DIM;  // [L, BS, H]

    cudaFuncSetAttribute(clt_gemm<true>,  cudaFuncAttributeMaxDynamicSharedMemorySize, SMEM_BYTES);
    cudaFuncSetAttribute(clt_gemm<false>, cudaFuncAttributeMaxDynamicSharedMemorySize, SMEM_BYTES);

    dim3 grid_enc(BS_DIM / TM, F_DIM / TN, L_DIM);   // 16 x 4 x 16
    clt_gemm<true><<<grid_enc, NTHREADS, SMEM_BYTES>>>(resid, enc_w, feats);

    dim3 grid_dec(BS_DIM / TM, H_DIM / TN, L_DIM);   // 16 x 16 x 16
    clt_gemm<false><<<grid_dec, NTHREADS, SMEM_BYTES>>>(feats, dec_w, recon);
}